// round 7
// baseline (speedup 1.0000x reference)
#include <cuda_runtime.h>
#include <math.h>

#define NT 256
#define FTS 114   // ftp row stride in u64 (912B, bank drift 4 -> 2-way max on RMW)
typedef unsigned long long u64;

__device__ __forceinline__ u64 pk2(float lo, float hi) {
    u64 r; asm("mov.b64 %0,{%1,%2};" : "=l"(r) : "f"(lo), "f"(hi)); return r;
}
__device__ __forceinline__ void upk2(u64 v, float& lo, float& hi) {
    asm("mov.b64 {%0,%1},%2;" : "=f"(lo), "=f"(hi) : "l"(v));
}
__device__ __forceinline__ void fma2(u64& d, u64 a, u64 b) {
    asm("fma.rn.f32x2 %0,%1,%2,%0;" : "+l"(d) : "l"(a), "l"(b));
}
__device__ __forceinline__ float hsum2(u64 v) {
    float lo, hi; upk2(v, lo, hi); return lo + hi;
}
__device__ __forceinline__ float fast_tanh(float x) {
    float t, r;
    asm("ex2.approx.f32 %0, %1;" : "=f"(t) : "f"(x * 2.885390082f));
    asm("rcp.approx.f32 %0, %1;" : "=f"(r) : "f"(t + 1.0f));
    return 1.0f - 2.0f * r;
}

struct __align__(16) Smem {
    union {
        float xs[3 * 34 * 34];       // phases 1-2
        u64   wcfp[16 * 64];         // depth loop: [icp][j][o8grp] interleaved
    } A;
    union {
        float p1p[8 * 17 * 17];      // phases 2-3
        struct { u64 weffp[16 * 32]; float beff[32]; } L;  // depth loop
    } B;
    union {
        float p2[16 * 49];           // phases 3-4
        float stage[32 * 64];        // conf staging [pos32][oc64]
    } C;
    u64    ftp[16 * FTS];            // feature map, channel-pair-major [icp][pos]
    float2 w1d[600];                 // conv1 [tap][oc] dup pairs
    float2 w2d[1152];                // conv2 [tap][oc] dup pairs
    u64    w3p[8 * 32];              // conv3 [icp][j][half] interleaved
    float  wcfc[1024];
    float  bcf[64];
    float  b1[8], b2[16], b3[32], bcfc;
    float  red[40];
    float  clsred[80];
};

__global__ __launch_bounds__(NT, 3)
void TM_20005957665089_kernel(
    const float* __restrict__ gx,
    const float* __restrict__ gw1,  const float* __restrict__ gb1,
    const float* __restrict__ gw2,  const float* __restrict__ gb2,
    const float* __restrict__ gw3,  const float* __restrict__ gb3,
    const float* __restrict__ gwcf, const float* __restrict__ gbcf,
    const float* __restrict__ gwcfc,const float* __restrict__ gbcfc,
    const float* __restrict__ gwq,  const float* __restrict__ gbq,
    const float* __restrict__ gwa,  const float* __restrict__ gba,
    const float* __restrict__ gwcls,const float* __restrict__ gbcls,
    float* __restrict__ gout)
{
    extern __shared__ float smem_raw[];
    Smem* s = reinterpret_cast<Smem*>(smem_raw);
    const int tid  = threadIdx.x;
    const int lane = tid & 31;
    const int wid  = tid >> 5;
    const int b    = blockIdx.x;

    // ---- Phase 0 ----
    for (int i = tid; i < 3468; i += NT) s->A.xs[i]  = 0.f;
    for (int i = tid; i < 2312; i += NT) s->B.p1p[i] = 0.f;
    for (int i = tid; i < 600; i += NT) {
        int oc = i / 75, r = i % 75;
        float v = gw1[i];
        s->w1d[r * 8 + oc] = make_float2(v, v);
    }
    for (int i = tid; i < 1152; i += NT) {
        int oc = i / 72, r = i % 72;
        float v = gw2[i];
        s->w2d[r * 16 + oc] = make_float2(v, v);
    }
    // w3p interleaved: entry (icp, oc) at u64 idx icp*32 + j*4 + half*2 + (oc&1),
    // j = (oc&15)>>1, half = oc>>4
    for (int i = tid; i < 512; i += NT) {
        int oc = i >> 4, ic = i & 15;
        int u = (ic >> 1) * 32 + ((oc & 15) >> 1) * 4 + (oc >> 4) * 2 + (oc & 1);
        ((float*)s->w3p)[u * 2 + (ic & 1)] = gw3[i];
    }
    for (int i = tid; i < 1024; i += NT) s->wcfc[i] = gwcfc[i];
    for (int i = tid; i < 64;   i += NT) s->bcf[i]  = gbcf[i];
    if (tid < 8)  s->b1[tid] = gb1[tid];
    if (tid < 16) s->b2[tid] = gb2[tid];
    if (tid < 32) s->b3[tid] = gb3[tid];
    if (tid == 0) s->bcfc = gbcfc[0];
    __syncthreads();

    // ---- Phase 1: x -> padded smem ----
    const float* xin = gx + (size_t)b * 3072;
    for (int i = tid; i < 3072; i += NT) {
        int c = i >> 10, r = (i >> 5) & 31, cc = i & 31;
        s->A.xs[c * 1156 + (r + 1) * 34 + (cc + 1)] = xin[i];
    }
    __syncthreads();

    // ---- Phase 2: conv1 (3->8, 5x5) + relu + maxpool2 ----
    if (tid < 225) {
        const int py = tid / 15, px = tid % 15;
        const int x0 = 2 * px, y0 = 2 * py;
        u64 acc[8][2];
        #pragma unroll
        for (int k = 0; k < 8; k++) { acc[k][0] = 0ull; acc[k][1] = 0ull; }
        #pragma unroll
        for (int ic = 0; ic < 3; ic++) {
            const float* xb = &s->A.xs[ic * 1156 + y0 * 34 + x0];   // 8B-aligned
            #pragma unroll
            for (int ky = 0; ky < 5; ky++) {
                const u64* pa64 = (const u64*)(xb + ky * 34);
                const u64* pb64 = (const u64*)(xb + ky * 34 + 34);
                u64 A0 = pa64[0], A1 = pa64[1], A2 = pa64[2];
                u64 B0 = pb64[0], B1 = pb64[1], B2 = pb64[2];
                float al0,ah0,al1,ah1,al2,ah2, bl0,bh0,bl1,bh1,bl2,bh2;
                upk2(A0,al0,ah0); upk2(A1,al1,ah1); upk2(A2,al2,ah2);
                upk2(B0,bl0,bh0); upk2(B1,bl1,bh1); upk2(B2,bl2,bh2);
                u64 pa2[5] = { A0, pk2(ah0, al1), A1, pk2(ah1, al2), A2 };
                u64 pb2[5] = { B0, pk2(bh0, bl1), B1, pk2(bh1, bl2), B2 };
                const ulonglong2* wp =
                    (const ulonglong2*)&s->w1d[(ic * 25 + ky * 5) * 8];
                #pragma unroll
                for (int kx = 0; kx < 5; kx++) {
                    #pragma unroll
                    for (int j = 0; j < 4; j++) {
                        ulonglong2 w2 = wp[kx * 4 + j];
                        fma2(acc[2*j  ][0], w2.x, pa2[kx]);
                        fma2(acc[2*j  ][1], w2.x, pb2[kx]);
                        fma2(acc[2*j+1][0], w2.y, pa2[kx]);
                        fma2(acc[2*j+1][1], w2.y, pb2[kx]);
                    }
                }
            }
        }
        #pragma unroll
        for (int k = 0; k < 8; k++) {
            float a0, a1, c0, c1;
            upk2(acc[k][0], a0, a1); upk2(acc[k][1], c0, c1);
            float m = fmaxf(fmaxf(a0, a1), fmaxf(c0, c1)) + s->b1[k];
            s->B.p1p[k * 289 + (py + 1) * 17 + (px + 1)] = fmaxf(m, 0.f);
        }
    }
    __syncthreads();

    // ---- Phase 2.5 (xs dead): wcfp interleaved fill + conv2 ----
    // entry (icp, oc) at u64 idx icp*64 + j*16 + g*2 + (oc&1), j=(oc&7)>>1, g=oc>>3
    for (int i = tid; i < 1024; i += NT) {
        int icp = i >> 6, oc = i & 63;
        int u = icp * 64 + ((oc & 7) >> 1) * 16 + (oc >> 3) * 2 + (oc & 1);
        s->A.wcfp[u] = pk2(gwcf[oc * 32 + 2 * icp], gwcf[oc * 32 + 2 * icp + 1]);
    }
    if (tid < 196) {
        const int ocg = tid / 49;
        const int pos = tid % 49;
        const int py = pos / 7, px = pos % 7;
        u64 acc[4][2];
        #pragma unroll
        for (int k = 0; k < 4; k++) { acc[k][0] = 0ull; acc[k][1] = 0ull; }
        #pragma unroll
        for (int ic = 0; ic < 8; ic++) {
            const float* pbase = &s->B.p1p[ic * 289 + 2 * py * 17 + 2 * px];
            #pragma unroll
            for (int ky = 0; ky < 3; ky++) {
                const float* pa = pbase + ky * 17;
                const float* pb = pa + 17;
                u64 pa2[3], pb2[3];
                #pragma unroll
                for (int kx = 0; kx < 3; kx++) {
                    pa2[kx] = pk2(pa[kx], pa[kx + 1]);
                    pb2[kx] = pk2(pb[kx], pb[kx + 1]);
                }
                const ulonglong2* wp =
                    (const ulonglong2*)&s->w2d[(ic * 9 + ky * 3) * 16 + ocg * 4];
                #pragma unroll
                for (int kx = 0; kx < 3; kx++) {
                    ulonglong2 wA = wp[kx * 8];
                    ulonglong2 wB = wp[kx * 8 + 1];
                    fma2(acc[0][0], wA.x, pa2[kx]); fma2(acc[0][1], wA.x, pb2[kx]);
                    fma2(acc[1][0], wA.y, pa2[kx]); fma2(acc[1][1], wA.y, pb2[kx]);
                    fma2(acc[2][0], wB.x, pa2[kx]); fma2(acc[2][1], wB.x, pb2[kx]);
                    fma2(acc[3][0], wB.y, pa2[kx]); fma2(acc[3][1], wB.y, pb2[kx]);
                }
            }
        }
        #pragma unroll
        for (int k = 0; k < 4; k++) {
            float a0, a1, c0, c1;
            upk2(acc[k][0], a0, a1); upk2(acc[k][1], c0, c1);
            float m = fmaxf(fmaxf(a0, a1), fmaxf(c0, c1)) + s->b2[ocg * 4 + k];
            s->C.p2[(ocg * 4 + k) * 49 + pos] = fmaxf(m, 0.f);
        }
    }
    __syncthreads();

    // ---- Phase 3.5 (p1p dead): weffp interleaved fill + conv3 -> ftp ----
    // entry (icp, oc) at u64 idx icp*32 + j*8 + g*2 + (oc&1), j=(oc&7)>>1, g=oc>>3
    for (int o = tid; o < 1024; o += NT) {
        int oc = o >> 5, ic = o & 31;
        float v = __ldg(&gwa[oc * 48 + 16 + ic]);
        #pragma unroll
        for (int j = 0; j < 16; j++)
            v += __ldg(&gwa[oc * 48 + j]) * __ldg(&gwq[j * 32 + ic]);
        int u = (ic >> 1) * 32 + ((oc & 7) >> 1) * 8 + (oc >> 3) * 2 + (oc & 1);
        ((float*)s->B.L.weffp)[u * 2 + (ic & 1)] = v;
    }
    if (tid < 32) {
        float v = __ldg(&gba[tid]);
        #pragma unroll
        for (int j = 0; j < 16; j++)
            v += __ldg(&gwa[tid * 48 + j]) * __ldg(&gbq[j]);
        s->B.L.beff[tid] = v;
    }
    // conv3: thread = (pos, half of 16 oc); writes 8 icp rows of ftp
    if (tid < 224) {
        const int pos  = tid >> 1;
        const int half = tid & 1;
        const int y = pos / 12, x = pos % 12;
        const bool valid_cell = (x < 9) && (y < 9);
        const bool interior = ((unsigned)(y - 1) < 7u) && ((unsigned)(x - 1) < 7u);
        if (interior) {
            const int pidx = (y - 1) * 7 + (x - 1);
            u64 acc[16];
            #pragma unroll
            for (int k = 0; k < 16; k++) acc[k] = 0ull;
            #pragma unroll
            for (int icp = 0; icp < 8; icp++) {
                u64 fd = pk2(s->C.p2[(2 * icp) * 49 + pidx],
                             s->C.p2[(2 * icp + 1) * 49 + pidx]);
                const ulonglong2* wp = (const ulonglong2*)&s->w3p[icp * 32 + half * 2];
                #pragma unroll
                for (int j = 0; j < 8; j++) {
                    ulonglong2 w2 = wp[j * 2];
                    fma2(acc[2*j],   w2.x, fd);
                    fma2(acc[2*j+1], w2.y, fd);
                }
            }
            #pragma unroll
            for (int jp = 0; jp < 8; jp++)
                s->ftp[(half * 8 + jp) * FTS + pos] =
                    pk2(hsum2(acc[2*jp])   + s->b3[half * 16 + 2*jp],
                        hsum2(acc[2*jp+1]) + s->b3[half * 16 + 2*jp + 1]);
        } else {
            #pragma unroll
            for (int jp = 0; jp < 8; jp++)
                s->ftp[(half * 8 + jp) * FTS + pos] =
                    valid_cell ? pk2(s->b3[half * 16 + 2*jp], s->b3[half * 16 + 2*jp + 1])
                               : 0ull;
        }
    }
    __syncthreads();

    // depth-loop roles
    const int o8 = lane >> 2, pp = lane & 3;        // conf: oc-oct, col-pair
    const int o4 = lane >> 3;                       // a: 8-oc group
    const int pi0 = lane & 7;
    const bool aact = pi0 < 7;
    const int pi = aact ? pi0 : 0;

    // ---- Phase 5: adaptive depth loop ----
    for (int depth = 0; depth < 8; depth++) {
        // --- conf pass 1: conv_cf at (row=wid, cols 2pp,2pp+1), col-max -> stage ---
        {
            const int cp0 = wid * 12 + 2 * pp;
            u64 acc[8][2];
            #pragma unroll
            for (int j = 0; j < 8; j++) { acc[j][0] = 0ull; acc[j][1] = 0ull; }
            #pragma unroll 4
            for (int icp = 0; icp < 16; icp++) {
                ulonglong2 fv = *(const ulonglong2*)&s->ftp[icp * FTS + cp0];
                const ulonglong2* wp = (const ulonglong2*)&s->A.wcfp[icp * 64 + o8 * 2];
                #pragma unroll
                for (int j = 0; j < 4; j++) {
                    ulonglong2 w2 = wp[j * 8];          // chunk j: 8 groups contiguous
                    fma2(acc[2*j  ][0], w2.x, fv.x); fma2(acc[2*j  ][1], w2.x, fv.y);
                    fma2(acc[2*j+1][0], w2.y, fv.x); fma2(acc[2*j+1][1], w2.y, fv.y);
                }
            }
            u64* strow = (u64*)&s->C.stage[(pp * 8 + wid) * 64 + o8 * 8];
            #pragma unroll
            for (int jp = 0; jp < 4; jp++) {
                float b0 = s->bcf[o8 * 8 + 2*jp];
                float b1 = s->bcf[o8 * 8 + 2*jp + 1];
                float m0 = fmaxf(hsum2(acc[2*jp][0]),   hsum2(acc[2*jp][1]))   + b0;
                float m1 = fmaxf(hsum2(acc[2*jp+1][0]), hsum2(acc[2*jp+1][1])) + b1;
                strow[jp] = pk2(m0, m1);
            }
        }
        __syncthreads();
        // --- conf pass 2: row-max + relu + dot wcfc ---
        {
            const int oc = tid & 63;
            const int k  = tid >> 6;
            float partial = 0.f;
            #pragma unroll
            for (int p = 0; p < 4; p++) {
                float r0 = s->C.stage[(p * 8 + 2 * k) * 64 + oc];
                float r1 = s->C.stage[(p * 8 + 2 * k + 1) * 64 + oc];
                float m = fmaxf(fmaxf(r0, r1), 0.f);
                partial += m * s->wcfc[oc * 16 + k * 4 + p];
            }
            #pragma unroll
            for (int o = 16; o > 0; o >>= 1)
                partial += __shfl_down_sync(0xffffffffu, partial, o);
            if (lane == 0) s->red[wid] = partial;
        }
        __syncthreads();
        if (tid == 0) {
            float logit = s->bcfc;
            #pragma unroll
            for (int w = 0; w < 8; w++) logit += s->red[w];
            float confv = 1.f / (1.f + expf(-logit));
            s->red[32] = (confv < 0.9f) ? 1.f : 0.f;
        }
        __syncthreads();
        if (s->red[32] == 0.f) break;

        // --- fused residual: f += tanh(W_eff @ f + b_eff) ---
        const int pos0 = wid * 14 + 2 * pi;
        u64 acc[8][2];
        #pragma unroll
        for (int j = 0; j < 8; j++) { acc[j][0] = 0ull; acc[j][1] = 0ull; }
        #pragma unroll 4
        for (int icp = 0; icp < 16; icp++) {
            ulonglong2 fv = *(const ulonglong2*)&s->ftp[icp * FTS + pos0];
            const ulonglong2* wp = (const ulonglong2*)&s->B.L.weffp[icp * 32 + o4 * 2];
            ulonglong2 wA = wp[0], wB = wp[4];      // chunks j=0,1
            fma2(acc[0][0], wA.x, fv.x); fma2(acc[0][1], wA.x, fv.y);
            fma2(acc[1][0], wA.y, fv.x); fma2(acc[1][1], wA.y, fv.y);
            fma2(acc[2][0], wB.x, fv.x); fma2(acc[2][1], wB.x, fv.y);
            fma2(acc[3][0], wB.y, fv.x); fma2(acc[3][1], wB.y, fv.y);
            wA = wp[8]; wB = wp[12];                // chunks j=2,3
            fma2(acc[4][0], wA.x, fv.x); fma2(acc[4][1], wA.x, fv.y);
            fma2(acc[5][0], wA.y, fv.x); fma2(acc[5][1], wA.y, fv.y);
            fma2(acc[6][0], wB.x, fv.x); fma2(acc[6][1], wB.x, fv.y);
            fma2(acc[7][0], wB.y, fv.x); fma2(acc[7][1], wB.y, fv.y);
        }
        __syncthreads();   // all reads of ftp complete before writes
        if (aact) {
            #pragma unroll
            for (int m = 0; m < 4; m++) {
                const int row = o4 * 4 + m;                 // icp row = oc pair
                ulonglong2* fp = (ulonglong2*)&s->ftp[row * FTS + pos0];
                ulonglong2 oldv = *fp;
                float e0, e1, f0, f1;
                upk2(oldv.x, e0, e1); upk2(oldv.y, f0, f1);
                float b0 = s->B.L.beff[o4 * 8 + 2*m];
                float b1 = s->B.L.beff[o4 * 8 + 2*m + 1];
                oldv.x = pk2(e0 + fast_tanh(hsum2(acc[2*m][0])   + b0),
                             e1 + fast_tanh(hsum2(acc[2*m+1][0]) + b1));
                oldv.y = pk2(f0 + fast_tanh(hsum2(acc[2*m][1])   + b0),
                             f1 + fast_tanh(hsum2(acc[2*m+1][1]) + b1));
                *fp = oldv;
            }
        }
        __syncthreads();
    }

    // ---- Phase 6: classifier ----
    {
        const float* ftf = (const float*)s->ftp;
        float ac[10];
        #pragma unroll
        for (int o = 0; o < 10; o++) ac[o] = 0.f;
        for (int i = tid; i < 2592; i += NT) {
            int ch = i / 81, r = i - ch * 81;
            int y = r / 9, x = r - 9 * y;
            int pos = y * 12 + x;
            float fv = ftf[(ch >> 1) * (2 * FTS) + pos * 2 + (ch & 1)];
            #pragma unroll
            for (int o = 0; o < 10; o++)
                ac[o] += __ldg(&gwcls[o * 2592 + i]) * fv;
        }
        #pragma unroll
        for (int o = 0; o < 10; o++) {
            float v = ac[o];
            #pragma unroll
            for (int sh = 16; sh > 0; sh >>= 1)
                v += __shfl_down_sync(0xffffffffu, v, sh);
            if (lane == 0) s->clsred[wid * 10 + o] = v;
        }
        __syncthreads();
        if (tid < 10) {
            float v = gbcls[tid];
            #pragma unroll
            for (int w = 0; w < 8; w++) v += s->clsred[w * 10 + tid];
            gout[(size_t)b * 10 + tid] = v;
        }
    }
}

extern "C" void kernel_launch(void* const* d_in, const int* in_sizes, int n_in,
                              void* d_out, int out_size) {
    const float* x     = (const float*)d_in[0];
    const float* w_b1  = (const float*)d_in[1];
    const float* b_b1  = (const float*)d_in[2];
    const float* w_b2  = (const float*)d_in[3];
    const float* b_b2  = (const float*)d_in[4];
    const float* w_b3  = (const float*)d_in[5];
    const float* b_b3  = (const float*)d_in[6];
    const float* w_cf  = (const float*)d_in[7];
    const float* b_cf  = (const float*)d_in[8];
    const float* w_cfc = (const float*)d_in[9];
    const float* b_cfc = (const float*)d_in[10];
    const float* w_q   = (const float*)d_in[11];
    const float* b_q   = (const float*)d_in[12];
    const float* w_a   = (const float*)d_in[13];
    const float* b_a   = (const float*)d_in[14];
    const float* w_cls = (const float*)d_in[15];
    const float* b_cls = (const float*)d_in[16];
    float* out = (float*)d_out;

    int B = in_sizes[0] / (3 * 32 * 32);
    size_t smem = sizeof(Smem);
    cudaFuncSetAttribute(TM_20005957665089_kernel,
                         cudaFuncAttributeMaxDynamicSharedMemorySize, (int)smem);
    TM_20005957665089_kernel<<<B, NT, smem>>>(
        x, w_b1, b_b1, w_b2, b_b2, w_b3, b_b3,
        w_cf, b_cf, w_cfc, b_cfc, w_q, b_q, w_a, b_a,
        w_cls, b_cls, out);
}

// round 8
// speedup vs baseline: 1.0299x; 1.0299x over previous
#include <cuda_runtime.h>
#include <math.h>

#define NT 256
#define FTS 98    // ftp row stride in u64 (784B, bank drift 4 -> 2-way max on RMW)
typedef unsigned long long u64;

__device__ __forceinline__ u64 pk2(float lo, float hi) {
    u64 r; asm("mov.b64 %0,{%1,%2};" : "=l"(r) : "f"(lo), "f"(hi)); return r;
}
__device__ __forceinline__ void upk2(u64 v, float& lo, float& hi) {
    asm("mov.b64 {%0,%1},%2;" : "=f"(lo), "=f"(hi) : "l"(v));
}
__device__ __forceinline__ void fma2(u64& d, u64 a, u64 b) {
    asm("fma.rn.f32x2 %0,%1,%2,%0;" : "+l"(d) : "l"(a), "l"(b));
}
__device__ __forceinline__ float hsum2(u64 v) {
    float lo, hi; upk2(v, lo, hi); return lo + hi;
}
__device__ __forceinline__ float fast_tanh(float x) {
    float t, r;
    asm("ex2.approx.f32 %0, %1;" : "=f"(t) : "f"(x * 2.885390082f));
    asm("rcp.approx.f32 %0, %1;" : "=f"(r) : "f"(t + 1.0f));
    return 1.0f - 2.0f * r;
}

struct __align__(16) Smem {
    union {
        float xs[3 * 34 * 34];       // phases 1-2
        u64   wcfp[16 * 64];         // depth loop: [icp][j][o8grp] interleaved
    } A;
    union {
        float p1p[8 * 17 * 17];      // phases 2-3
        struct { u64 weffp[16 * 32]; float beff[32]; } L;  // depth loop
    } B;
    union {
        float p2[16 * 49];           // phases 3-4
        float stage[32 * 64];        // conf staging [pos32][oc64]
    } C;
    u64    ftp[16 * FTS];            // feature map [icp][pos], pos = y*10+x (0..95)
    float2 w1d[600];                 // conv1 [tap][oc] dup pairs
    float2 w2d[1152];                // conv2 [tap][oc] dup pairs
    u64    w3p[8 * 32];              // conv3 [icp][j][half] interleaved
    float  wcfc[1024];
    float  bcf[64];
    float  b1[8], b2[16], b3[32], bcfc;
    float  red[40];
    float  clsred[80];
};

__global__ __launch_bounds__(NT, 3)
void TM_20005957665089_kernel(
    const float* __restrict__ gx,
    const float* __restrict__ gw1,  const float* __restrict__ gb1,
    const float* __restrict__ gw2,  const float* __restrict__ gb2,
    const float* __restrict__ gw3,  const float* __restrict__ gb3,
    const float* __restrict__ gwcf, const float* __restrict__ gbcf,
    const float* __restrict__ gwcfc,const float* __restrict__ gbcfc,
    const float* __restrict__ gwq,  const float* __restrict__ gbq,
    const float* __restrict__ gwa,  const float* __restrict__ gba,
    const float* __restrict__ gwcls,const float* __restrict__ gbcls,
    float* __restrict__ gout)
{
    extern __shared__ float smem_raw[];
    Smem* s = reinterpret_cast<Smem*>(smem_raw);
    const int tid  = threadIdx.x;
    const int lane = tid & 31;
    const int wid  = tid >> 5;
    const int b    = blockIdx.x;

    // ---- Phase 0 ----
    for (int i = tid; i < 3468; i += NT) s->A.xs[i]  = 0.f;
    for (int i = tid; i < 2312; i += NT) s->B.p1p[i] = 0.f;
    for (int i = tid; i < 600; i += NT) {
        int oc = i / 75, r = i % 75;
        float v = gw1[i];
        s->w1d[r * 8 + oc] = make_float2(v, v);
    }
    for (int i = tid; i < 1152; i += NT) {
        int oc = i / 72, r = i % 72;
        float v = gw2[i];
        s->w2d[r * 16 + oc] = make_float2(v, v);
    }
    // w3p interleaved: entry (icp, oc) at u64 idx icp*32 + j*4 + half*2 + (oc&1)
    for (int i = tid; i < 512; i += NT) {
        int oc = i >> 4, ic = i & 15;
        int u = (ic >> 1) * 32 + ((oc & 15) >> 1) * 4 + (oc >> 4) * 2 + (oc & 1);
        ((float*)s->w3p)[u * 2 + (ic & 1)] = gw3[i];
    }
    for (int i = tid; i < 1024; i += NT) s->wcfc[i] = gwcfc[i];
    for (int i = tid; i < 64;   i += NT) s->bcf[i]  = gbcf[i];
    if (tid < 8)  s->b1[tid] = gb1[tid];
    if (tid < 16) s->b2[tid] = gb2[tid];
    if (tid < 32) s->b3[tid] = gb3[tid];
    if (tid == 0) s->bcfc = gbcfc[0];
    __syncthreads();

    // ---- Phase 1: x -> padded smem ----
    const float* xin = gx + (size_t)b * 3072;
    for (int i = tid; i < 3072; i += NT) {
        int c = i >> 10, r = (i >> 5) & 31, cc = i & 31;
        s->A.xs[c * 1156 + (r + 1) * 34 + (cc + 1)] = xin[i];
    }
    __syncthreads();

    // ---- Phase 2: conv1 (3->8, 5x5) + relu + maxpool2 ----
    if (tid < 225) {
        const int py = tid / 15, px = tid % 15;
        const int x0 = 2 * px, y0 = 2 * py;
        u64 acc[8][2];
        #pragma unroll
        for (int k = 0; k < 8; k++) { acc[k][0] = 0ull; acc[k][1] = 0ull; }
        #pragma unroll
        for (int ic = 0; ic < 3; ic++) {
            const float* xb = &s->A.xs[ic * 1156 + y0 * 34 + x0];   // 8B-aligned
            #pragma unroll
            for (int ky = 0; ky < 5; ky++) {
                const u64* pa64 = (const u64*)(xb + ky * 34);
                const u64* pb64 = (const u64*)(xb + ky * 34 + 34);
                u64 A0 = pa64[0], A1 = pa64[1], A2 = pa64[2];
                u64 B0 = pb64[0], B1 = pb64[1], B2 = pb64[2];
                float al0,ah0,al1,ah1,al2,ah2, bl0,bh0,bl1,bh1,bl2,bh2;
                upk2(A0,al0,ah0); upk2(A1,al1,ah1); upk2(A2,al2,ah2);
                upk2(B0,bl0,bh0); upk2(B1,bl1,bh1); upk2(B2,bl2,bh2);
                u64 pa2[5] = { A0, pk2(ah0, al1), A1, pk2(ah1, al2), A2 };
                u64 pb2[5] = { B0, pk2(bh0, bl1), B1, pk2(bh1, bl2), B2 };
                const ulonglong2* wp =
                    (const ulonglong2*)&s->w1d[(ic * 25 + ky * 5) * 8];
                #pragma unroll
                for (int kx = 0; kx < 5; kx++) {
                    #pragma unroll
                    for (int j = 0; j < 4; j++) {
                        ulonglong2 w2 = wp[kx * 4 + j];
                        fma2(acc[2*j  ][0], w2.x, pa2[kx]);
                        fma2(acc[2*j  ][1], w2.x, pb2[kx]);
                        fma2(acc[2*j+1][0], w2.y, pa2[kx]);
                        fma2(acc[2*j+1][1], w2.y, pb2[kx]);
                    }
                }
            }
        }
        #pragma unroll
        for (int k = 0; k < 8; k++) {
            float a0, a1, c0, c1;
            upk2(acc[k][0], a0, a1); upk2(acc[k][1], c0, c1);
            float m = fmaxf(fmaxf(a0, a1), fmaxf(c0, c1)) + s->b1[k];
            s->B.p1p[k * 289 + (py + 1) * 17 + (px + 1)] = fmaxf(m, 0.f);
        }
    }
    __syncthreads();

    // ---- Phase 2.5 (xs dead): wcfp interleaved fill + conv2 ----
    // entry (icp, oc) at u64 idx icp*64 + j*16 + g*2 + (oc&1), j=(oc&7)>>1, g=oc>>3
    for (int i = tid; i < 1024; i += NT) {
        int icp = i >> 6, oc = i & 63;
        int u = icp * 64 + ((oc & 7) >> 1) * 16 + (oc >> 3) * 2 + (oc & 1);
        s->A.wcfp[u] = pk2(gwcf[oc * 32 + 2 * icp], gwcf[oc * 32 + 2 * icp + 1]);
    }
    if (tid < 196) {
        const int ocg = tid / 49;
        const int pos = tid % 49;
        const int py = pos / 7, px = pos % 7;
        u64 acc[4][2];
        #pragma unroll
        for (int k = 0; k < 4; k++) { acc[k][0] = 0ull; acc[k][1] = 0ull; }
        #pragma unroll
        for (int ic = 0; ic < 8; ic++) {
            const float* pbase = &s->B.p1p[ic * 289 + 2 * py * 17 + 2 * px];
            #pragma unroll
            for (int ky = 0; ky < 3; ky++) {
                const float* pa = pbase + ky * 17;
                const float* pb = pa + 17;
                u64 pa2[3], pb2[3];
                #pragma unroll
                for (int kx = 0; kx < 3; kx++) {
                    pa2[kx] = pk2(pa[kx], pa[kx + 1]);
                    pb2[kx] = pk2(pb[kx], pb[kx + 1]);
                }
                const ulonglong2* wp =
                    (const ulonglong2*)&s->w2d[(ic * 9 + ky * 3) * 16 + ocg * 4];
                #pragma unroll
                for (int kx = 0; kx < 3; kx++) {
                    ulonglong2 wA = wp[kx * 8];
                    ulonglong2 wB = wp[kx * 8 + 1];
                    fma2(acc[0][0], wA.x, pa2[kx]); fma2(acc[0][1], wA.x, pb2[kx]);
                    fma2(acc[1][0], wA.y, pa2[kx]); fma2(acc[1][1], wA.y, pb2[kx]);
                    fma2(acc[2][0], wB.x, pa2[kx]); fma2(acc[2][1], wB.x, pb2[kx]);
                    fma2(acc[3][0], wB.y, pa2[kx]); fma2(acc[3][1], wB.y, pb2[kx]);
                }
            }
        }
        #pragma unroll
        for (int k = 0; k < 4; k++) {
            float a0, a1, c0, c1;
            upk2(acc[k][0], a0, a1); upk2(acc[k][1], c0, c1);
            float m = fmaxf(fmaxf(a0, a1), fmaxf(c0, c1)) + s->b2[ocg * 4 + k];
            s->C.p2[(ocg * 4 + k) * 49 + pos] = fmaxf(m, 0.f);
        }
    }
    __syncthreads();

    // ---- Phase 3.5 (p1p dead): weffp interleaved fill + conv3 -> ftp ----
    // entry (icp, oc) at u64 idx icp*32 + j*8 + g*2 + (oc&1), j=(oc&7)>>1, g=oc>>3
    for (int o = tid; o < 1024; o += NT) {
        int oc = o >> 5, ic = o & 31;
        float v = __ldg(&gwa[oc * 48 + 16 + ic]);
        #pragma unroll
        for (int j = 0; j < 16; j++)
            v += __ldg(&gwa[oc * 48 + j]) * __ldg(&gwq[j * 32 + ic]);
        int u = (ic >> 1) * 32 + ((oc & 7) >> 1) * 8 + (oc >> 3) * 2 + (oc & 1);
        ((float*)s->B.L.weffp)[u * 2 + (ic & 1)] = v;
    }
    if (tid < 32) {
        float v = __ldg(&gba[tid]);
        #pragma unroll
        for (int j = 0; j < 16; j++)
            v += __ldg(&gwa[tid * 48 + j]) * __ldg(&gbq[j]);
        s->B.L.beff[tid] = v;
    }
    // conv3: thread = (pos 0..95, half of 16 oc); pos = y*10 + x
    if (tid < 192) {
        const int pos  = tid >> 1;
        const int half = tid & 1;
        const int y = pos / 10, x = pos % 10;
        const bool valid_cell = (x < 9) && (y < 9);
        const bool interior = ((unsigned)(y - 1) < 7u) && ((unsigned)(x - 1) < 7u);
        if (interior) {
            const int pidx = (y - 1) * 7 + (x - 1);
            u64 acc[16];
            #pragma unroll
            for (int k = 0; k < 16; k++) acc[k] = 0ull;
            #pragma unroll
            for (int icp = 0; icp < 8; icp++) {
                u64 fd = pk2(s->C.p2[(2 * icp) * 49 + pidx],
                             s->C.p2[(2 * icp + 1) * 49 + pidx]);
                const ulonglong2* wp = (const ulonglong2*)&s->w3p[icp * 32 + half * 2];
                #pragma unroll
                for (int j = 0; j < 8; j++) {
                    ulonglong2 w2 = wp[j * 2];
                    fma2(acc[2*j],   w2.x, fd);
                    fma2(acc[2*j+1], w2.y, fd);
                }
            }
            #pragma unroll
            for (int jp = 0; jp < 8; jp++)
                s->ftp[(half * 8 + jp) * FTS + pos] =
                    pk2(hsum2(acc[2*jp])   + s->b3[half * 16 + 2*jp],
                        hsum2(acc[2*jp+1]) + s->b3[half * 16 + 2*jp + 1]);
        } else {
            #pragma unroll
            for (int jp = 0; jp < 8; jp++)
                s->ftp[(half * 8 + jp) * FTS + pos] =
                    valid_cell ? pk2(s->b3[half * 16 + 2*jp], s->b3[half * 16 + 2*jp + 1])
                               : 0ull;
        }
    }
    __syncthreads();

    // depth-loop roles
    const int o8 = lane >> 2, pp = lane & 3;        // conf: oc-oct, col-pair
    const int o4 = lane >> 3;                       // a-conv: 8-oc group
    const int pairk = wid * 8 + (lane & 7);         // a-conv: pos-pair 0..47 (warps 0..5)
    const bool aact = wid < 6;

    // ---- Phase 5: adaptive depth loop ----
    for (int depth = 0; depth < 8; depth++) {
        // --- conf pass 1: conv_cf at (row=wid, cols 2pp,2pp+1), col-max -> stage ---
        {
            const int cp0 = wid * 10 + 2 * pp;
            u64 acc[8][2];
            #pragma unroll
            for (int j = 0; j < 8; j++) { acc[j][0] = 0ull; acc[j][1] = 0ull; }
            #pragma unroll 4
            for (int icp = 0; icp < 16; icp++) {
                ulonglong2 fv = *(const ulonglong2*)&s->ftp[icp * FTS + cp0];
                const ulonglong2* wp = (const ulonglong2*)&s->A.wcfp[icp * 64 + o8 * 2];
                #pragma unroll
                for (int j = 0; j < 4; j++) {
                    ulonglong2 w2 = wp[j * 8];          // chunk j: 8 groups contiguous
                    fma2(acc[2*j  ][0], w2.x, fv.x); fma2(acc[2*j  ][1], w2.x, fv.y);
                    fma2(acc[2*j+1][0], w2.y, fv.x); fma2(acc[2*j+1][1], w2.y, fv.y);
                }
            }
            u64* strow = (u64*)&s->C.stage[(pp * 8 + wid) * 64 + o8 * 8];
            #pragma unroll
            for (int jp = 0; jp < 4; jp++) {
                float b0 = s->bcf[o8 * 8 + 2*jp];
                float b1 = s->bcf[o8 * 8 + 2*jp + 1];
                float m0 = fmaxf(hsum2(acc[2*jp][0]),   hsum2(acc[2*jp][1]))   + b0;
                float m1 = fmaxf(hsum2(acc[2*jp+1][0]), hsum2(acc[2*jp+1][1])) + b1;
                strow[jp] = pk2(m0, m1);
            }
        }
        __syncthreads();
        // --- conf pass 2: row-max + relu + dot wcfc ---
        {
            const int oc = tid & 63;
            const int k  = tid >> 6;
            float partial = 0.f;
            #pragma unroll
            for (int p = 0; p < 4; p++) {
                float r0 = s->C.stage[(p * 8 + 2 * k) * 64 + oc];
                float r1 = s->C.stage[(p * 8 + 2 * k + 1) * 64 + oc];
                float m = fmaxf(fmaxf(r0, r1), 0.f);
                partial += m * s->wcfc[oc * 16 + k * 4 + p];
            }
            #pragma unroll
            for (int o = 16; o > 0; o >>= 1)
                partial += __shfl_down_sync(0xffffffffu, partial, o);
            if (lane == 0) s->red[wid] = partial;
        }
        __syncthreads();
        if (tid == 0) {
            float logit = s->bcfc;
            #pragma unroll
            for (int w = 0; w < 8; w++) logit += s->red[w];
            // conf < 0.9  <=>  logit < ln(9)
            s->red[32] = (logit < 2.1972245773362196f) ? 1.f : 0.f;
        }
        __syncthreads();
        if (s->red[32] == 0.f) break;

        // --- fused residual: f += tanh(W_eff @ f + b_eff) ; 6 warps, 48 pairs ---
        const int pos0 = 2 * pairk;
        u64 acc[8][2];
        #pragma unroll
        for (int j = 0; j < 8; j++) { acc[j][0] = 0ull; acc[j][1] = 0ull; }
        if (aact) {
            #pragma unroll 4
            for (int icp = 0; icp < 16; icp++) {
                ulonglong2 fv = *(const ulonglong2*)&s->ftp[icp * FTS + pos0];
                const ulonglong2* wp = (const ulonglong2*)&s->B.L.weffp[icp * 32 + o4 * 2];
                ulonglong2 wA = wp[0], wB = wp[4];      // chunks j=0,1
                fma2(acc[0][0], wA.x, fv.x); fma2(acc[0][1], wA.x, fv.y);
                fma2(acc[1][0], wA.y, fv.x); fma2(acc[1][1], wA.y, fv.y);
                fma2(acc[2][0], wB.x, fv.x); fma2(acc[2][1], wB.x, fv.y);
                fma2(acc[3][0], wB.y, fv.x); fma2(acc[3][1], wB.y, fv.y);
                wA = wp[8]; wB = wp[12];                // chunks j=2,3
                fma2(acc[4][0], wA.x, fv.x); fma2(acc[4][1], wA.x, fv.y);
                fma2(acc[5][0], wA.y, fv.x); fma2(acc[5][1], wA.y, fv.y);
                fma2(acc[6][0], wB.x, fv.x); fma2(acc[6][1], wB.x, fv.y);
                fma2(acc[7][0], wB.y, fv.x); fma2(acc[7][1], wB.y, fv.y);
            }
        }
        __syncthreads();   // all reads of ftp complete before writes
        if (aact) {
            #pragma unroll
            for (int m = 0; m < 4; m++) {
                const int row = o4 * 4 + m;                 // icp row = oc pair
                ulonglong2* fp = (ulonglong2*)&s->ftp[row * FTS + pos0];
                ulonglong2 oldv = *fp;
                float e0, e1, f0, f1;
                upk2(oldv.x, e0, e1); upk2(oldv.y, f0, f1);
                float b0 = s->B.L.beff[o4 * 8 + 2*m];
                float b1 = s->B.L.beff[o4 * 8 + 2*m + 1];
                oldv.x = pk2(e0 + fast_tanh(hsum2(acc[2*m][0])   + b0),
                             e1 + fast_tanh(hsum2(acc[2*m+1][0]) + b1));
                oldv.y = pk2(f0 + fast_tanh(hsum2(acc[2*m][1])   + b0),
                             f1 + fast_tanh(hsum2(acc[2*m+1][1]) + b1));
                *fp = oldv;
            }
        }
        __syncthreads();
    }

    // ---- Phase 6: classifier (float4 LDG over w_cls) ----
    {
        const float* ftf = (const float*)s->ftp;
        float ac[10];
        #pragma unroll
        for (int o = 0; o < 10; o++) ac[o] = 0.f;
        #pragma unroll
        for (int k = 0; k < 3; k++) {
            int i4 = tid + k * NT;
            if (i4 < 648) {
                int i = i4 * 4;
                float fv[4];
                #pragma unroll
                for (int t = 0; t < 4; t++) {
                    int ii = i + t;
                    int ch = ii / 81;
                    int r  = ii - ch * 81;
                    int y  = r / 9, x = r - 9 * y;
                    fv[t] = ftf[(ch >> 1) * (2 * FTS) + (y * 10 + x) * 2 + (ch & 1)];
                }
                #pragma unroll
                for (int o = 0; o < 10; o++) {
                    float4 w4 = *(const float4*)&gwcls[o * 2592 + i];
                    ac[o] += w4.x * fv[0] + w4.y * fv[1] + w4.z * fv[2] + w4.w * fv[3];
                }
            }
        }
        #pragma unroll
        for (int o = 0; o < 10; o++) {
            float v = ac[o];
            #pragma unroll
            for (int sh = 16; sh > 0; sh >>= 1)
                v += __shfl_down_sync(0xffffffffu, v, sh);
            if (lane == 0) s->clsred[wid * 10 + o] = v;
        }
        __syncthreads();
        if (tid < 10) {
            float v = gbcls[tid];
            #pragma unroll
            for (int w = 0; w < 8; w++) v += s->clsred[w * 10 + tid];
            gout[(size_t)b * 10 + tid] = v;
        }
    }
}

extern "C" void kernel_launch(void* const* d_in, const int* in_sizes, int n_in,
                              void* d_out, int out_size) {
    const float* x     = (const float*)d_in[0];
    const float* w_b1  = (const float*)d_in[1];
    const float* b_b1  = (const float*)d_in[2];
    const float* w_b2  = (const float*)d_in[3];
    const float* b_b2  = (const float*)d_in[4];
    const float* w_b3  = (const float*)d_in[5];
    const float* b_b3  = (const float*)d_in[6];
    const float* w_cf  = (const float*)d_in[7];
    const float* b_cf  = (const float*)d_in[8];
    const float* w_cfc = (const float*)d_in[9];
    const float* b_cfc = (const float*)d_in[10];
    const float* w_q   = (const float*)d_in[11];
    const float* b_q   = (const float*)d_in[12];
    const float* w_a   = (const float*)d_in[13];
    const float* b_a   = (const float*)d_in[14];
    const float* w_cls = (const float*)d_in[15];
    const float* b_cls = (const float*)d_in[16];
    float* out = (float*)d_out;

    int B = in_sizes[0] / (3 * 32 * 32);
    size_t smem = sizeof(Smem);
    cudaFuncSetAttribute(TM_20005957665089_kernel,
                         cudaFuncAttributeMaxDynamicSharedMemorySize, (int)smem);
    TM_20005957665089_kernel<<<B, NT, smem>>>(
        x, w_b1, b_b1, w_b2, b_b2, w_b3, b_b3,
        w_cf, b_cf, w_cfc, b_cfc, w_q, b_q, w_a, b_a,
        w_cls, b_cls, out);
}

// round 9
// speedup vs baseline: 1.0644x; 1.0335x over previous
#include <cuda_runtime.h>
#include <math.h>

#define NT 256
#define FTS 98    // ftp row stride in u64 (784B, bank drift 4 -> 2-way max on RMW)
typedef unsigned long long u64;

__device__ __forceinline__ u64 pk2(float lo, float hi) {
    u64 r; asm("mov.b64 %0,{%1,%2};" : "=l"(r) : "f"(lo), "f"(hi)); return r;
}
__device__ __forceinline__ void upk2(u64 v, float& lo, float& hi) {
    asm("mov.b64 {%0,%1},%2;" : "=f"(lo), "=f"(hi) : "l"(v));
}
__device__ __forceinline__ void fma2(u64& d, u64 a, u64 b) {
    asm("fma.rn.f32x2 %0,%1,%2,%0;" : "+l"(d) : "l"(a), "l"(b));
}
__device__ __forceinline__ float hsum2(u64 v) {
    float lo, hi; upk2(v, lo, hi); return lo + hi;
}
__device__ __forceinline__ float fast_tanh(float x) {
    float t, r;
    asm("ex2.approx.f32 %0, %1;" : "=f"(t) : "f"(x * 2.885390082f));
    asm("rcp.approx.f32 %0, %1;" : "=f"(r) : "f"(t + 1.0f));
    return 1.0f - 2.0f * r;
}

struct __align__(16) Smem {
    union {
        float xs[3 * 34 * 34];       // phases 1-2
        u64   wcfp[16 * 64];         // depth loop: [icp][j][o8grp] interleaved
    } A;
    union {
        float p1p[8 * 17 * 17];      // phases 2-3
        struct { u64 weffp[16 * 32]; float beff[32]; } L;  // depth loop
    } B;
    float  p2[16 * 49];              // phases 3-4
    u64    ftp[16 * FTS];            // feature map [icp][pos], pos = y*10+x (0..95)
    float2 w1d[600];                 // conv1 [tap][oc] dup pairs
    float2 w2d[1152];                // conv2 [tap][oc] dup pairs
    u64    w3p[8 * 32];              // conv3 [icp][j][half] interleaved
    float  wcfcT[16 * 68];           // conf fc weights transposed [pooledpos][oc], row-pad 68
    float  bcf[64];
    float  b1[8], b2[16], b3[32];
    float  red[40];
    float  clsred[80];
    float  bcfc;
};

__global__ __launch_bounds__(NT, 3)
void TM_20005957665089_kernel(
    const float* __restrict__ gx,
    const float* __restrict__ gw1,  const float* __restrict__ gb1,
    const float* __restrict__ gw2,  const float* __restrict__ gb2,
    const float* __restrict__ gw3,  const float* __restrict__ gb3,
    const float* __restrict__ gwcf, const float* __restrict__ gbcf,
    const float* __restrict__ gwcfc,const float* __restrict__ gbcfc,
    const float* __restrict__ gwq,  const float* __restrict__ gbq,
    const float* __restrict__ gwa,  const float* __restrict__ gba,
    const float* __restrict__ gwcls,const float* __restrict__ gbcls,
    float* __restrict__ gout)
{
    extern __shared__ float smem_raw[];
    Smem* s = reinterpret_cast<Smem*>(smem_raw);
    const int tid  = threadIdx.x;
    const int lane = tid & 31;
    const int wid  = tid >> 5;
    const int b    = blockIdx.x;

    // ---- Phase 0 ----
    for (int i = tid; i < 3468; i += NT) s->A.xs[i]  = 0.f;
    for (int i = tid; i < 2312; i += NT) s->B.p1p[i] = 0.f;
    for (int i = tid; i < 600; i += NT) {
        int oc = i / 75, r = i % 75;
        float v = gw1[i];
        s->w1d[r * 8 + oc] = make_float2(v, v);
    }
    for (int i = tid; i < 1152; i += NT) {
        int oc = i / 72, r = i % 72;
        float v = gw2[i];
        s->w2d[r * 16 + oc] = make_float2(v, v);
    }
    // w3p interleaved: entry (icp, oc) at u64 idx icp*32 + j*4 + half*2 + (oc&1)
    for (int i = tid; i < 512; i += NT) {
        int oc = i >> 4, ic = i & 15;
        int u = (ic >> 1) * 32 + ((oc & 15) >> 1) * 4 + (oc >> 4) * 2 + (oc & 1);
        ((float*)s->w3p)[u * 2 + (ic & 1)] = gw3[i];
    }
    // wcfcT[p][oc] = w_cfc[oc*16 + p]
    for (int i = tid; i < 1024; i += NT) {
        int p = i >> 6, c = i & 63;
        s->wcfcT[p * 68 + c] = gwcfc[c * 16 + p];
    }
    for (int i = tid; i < 64; i += NT) s->bcf[i] = gbcf[i];
    if (tid < 8)  s->b1[tid] = gb1[tid];
    if (tid < 16) s->b2[tid] = gb2[tid];
    if (tid < 32) s->b3[tid] = gb3[tid];
    if (tid == 0) s->bcfc = gbcfc[0];
    __syncthreads();

    // ---- Phase 1: x -> padded smem ----
    const float* xin = gx + (size_t)b * 3072;
    for (int i = tid; i < 3072; i += NT) {
        int c = i >> 10, r = (i >> 5) & 31, cc = i & 31;
        s->A.xs[c * 1156 + (r + 1) * 34 + (cc + 1)] = xin[i];
    }
    __syncthreads();

    // ---- Phase 2: conv1 (3->8, 5x5) + relu + maxpool2 ----
    if (tid < 225) {
        const int py = tid / 15, px = tid % 15;
        const int x0 = 2 * px, y0 = 2 * py;
        u64 acc[8][2];
        #pragma unroll
        for (int k = 0; k < 8; k++) { acc[k][0] = 0ull; acc[k][1] = 0ull; }
        #pragma unroll
        for (int ic = 0; ic < 3; ic++) {
            const float* xb = &s->A.xs[ic * 1156 + y0 * 34 + x0];   // 8B-aligned
            #pragma unroll
            for (int ky = 0; ky < 5; ky++) {
                const u64* pa64 = (const u64*)(xb + ky * 34);
                const u64* pb64 = (const u64*)(xb + ky * 34 + 34);
                u64 A0 = pa64[0], A1 = pa64[1], A2 = pa64[2];
                u64 B0 = pb64[0], B1 = pb64[1], B2 = pb64[2];
                float al0,ah0,al1,ah1,al2,ah2, bl0,bh0,bl1,bh1,bl2,bh2;
                upk2(A0,al0,ah0); upk2(A1,al1,ah1); upk2(A2,al2,ah2);
                upk2(B0,bl0,bh0); upk2(B1,bl1,bh1); upk2(B2,bl2,bh2);
                u64 pa2[5] = { A0, pk2(ah0, al1), A1, pk2(ah1, al2), A2 };
                u64 pb2[5] = { B0, pk2(bh0, bl1), B1, pk2(bh1, bl2), B2 };
                const ulonglong2* wp =
                    (const ulonglong2*)&s->w1d[(ic * 25 + ky * 5) * 8];
                #pragma unroll
                for (int kx = 0; kx < 5; kx++) {
                    #pragma unroll
                    for (int j = 0; j < 4; j++) {
                        ulonglong2 w2 = wp[kx * 4 + j];
                        fma2(acc[2*j  ][0], w2.x, pa2[kx]);
                        fma2(acc[2*j  ][1], w2.x, pb2[kx]);
                        fma2(acc[2*j+1][0], w2.y, pa2[kx]);
                        fma2(acc[2*j+1][1], w2.y, pb2[kx]);
                    }
                }
            }
        }
        #pragma unroll
        for (int k = 0; k < 8; k++) {
            float a0, a1, c0, c1;
            upk2(acc[k][0], a0, a1); upk2(acc[k][1], c0, c1);
            float m = fmaxf(fmaxf(a0, a1), fmaxf(c0, c1)) + s->b1[k];
            s->B.p1p[k * 289 + (py + 1) * 17 + (px + 1)] = fmaxf(m, 0.f);
        }
    }
    __syncthreads();

    // ---- Phase 2.5 (xs dead): wcfp interleaved fill + conv2 ----
    // entry (icp, oc) at u64 idx icp*64 + j*16 + g*2 + (oc&1), j=(oc&7)>>1, g=oc>>3
    for (int i = tid; i < 1024; i += NT) {
        int icp = i >> 6, oc = i & 63;
        int u = icp * 64 + ((oc & 7) >> 1) * 16 + (oc >> 3) * 2 + (oc & 1);
        s->A.wcfp[u] = pk2(gwcf[oc * 32 + 2 * icp], gwcf[oc * 32 + 2 * icp + 1]);
    }
    if (tid < 196) {
        const int ocg = tid / 49;
        const int pos = tid % 49;
        const int py = pos / 7, px = pos % 7;
        u64 acc[4][2];
        #pragma unroll
        for (int k = 0; k < 4; k++) { acc[k][0] = 0ull; acc[k][1] = 0ull; }
        #pragma unroll
        for (int ic = 0; ic < 8; ic++) {
            const float* pbase = &s->B.p1p[ic * 289 + 2 * py * 17 + 2 * px];
            #pragma unroll
            for (int ky = 0; ky < 3; ky++) {
                const float* pa = pbase + ky * 17;
                const float* pb = pa + 17;
                u64 pa2[3], pb2[3];
                #pragma unroll
                for (int kx = 0; kx < 3; kx++) {
                    pa2[kx] = pk2(pa[kx], pa[kx + 1]);
                    pb2[kx] = pk2(pb[kx], pb[kx + 1]);
                }
                const ulonglong2* wp =
                    (const ulonglong2*)&s->w2d[(ic * 9 + ky * 3) * 16 + ocg * 4];
                #pragma unroll
                for (int kx = 0; kx < 3; kx++) {
                    ulonglong2 wA = wp[kx * 8];
                    ulonglong2 wB = wp[kx * 8 + 1];
                    fma2(acc[0][0], wA.x, pa2[kx]); fma2(acc[0][1], wA.x, pb2[kx]);
                    fma2(acc[1][0], wA.y, pa2[kx]); fma2(acc[1][1], wA.y, pb2[kx]);
                    fma2(acc[2][0], wB.x, pa2[kx]); fma2(acc[2][1], wB.x, pb2[kx]);
                    fma2(acc[3][0], wB.y, pa2[kx]); fma2(acc[3][1], wB.y, pb2[kx]);
                }
            }
        }
        #pragma unroll
        for (int k = 0; k < 4; k++) {
            float a0, a1, c0, c1;
            upk2(acc[k][0], a0, a1); upk2(acc[k][1], c0, c1);
            float m = fmaxf(fmaxf(a0, a1), fmaxf(c0, c1)) + s->b2[ocg * 4 + k];
            s->p2[(ocg * 4 + k) * 49 + pos] = fmaxf(m, 0.f);
        }
    }
    __syncthreads();

    // ---- Phase 3.5 (p1p dead): weffp interleaved fill + conv3 -> ftp ----
    for (int o = tid; o < 1024; o += NT) {
        int oc = o >> 5, ic = o & 31;
        float v = __ldg(&gwa[oc * 48 + 16 + ic]);
        #pragma unroll
        for (int j = 0; j < 16; j++)
            v += __ldg(&gwa[oc * 48 + j]) * __ldg(&gwq[j * 32 + ic]);
        int u = (ic >> 1) * 32 + ((oc & 7) >> 1) * 8 + (oc >> 3) * 2 + (oc & 1);
        ((float*)s->B.L.weffp)[u * 2 + (ic & 1)] = v;
    }
    if (tid < 32) {
        float v = __ldg(&gba[tid]);
        #pragma unroll
        for (int j = 0; j < 16; j++)
            v += __ldg(&gwa[tid * 48 + j]) * __ldg(&gbq[j]);
        s->B.L.beff[tid] = v;
    }
    // conv3: thread = (pos 0..95, half of 16 oc); pos = y*10 + x
    if (tid < 192) {
        const int pos  = tid >> 1;
        const int half = tid & 1;
        const int y = pos / 10, x = pos % 10;
        const bool valid_cell = (x < 9) && (y < 9);
        const bool interior = ((unsigned)(y - 1) < 7u) && ((unsigned)(x - 1) < 7u);
        if (interior) {
            const int pidx = (y - 1) * 7 + (x - 1);
            u64 acc[16];
            #pragma unroll
            for (int k = 0; k < 16; k++) acc[k] = 0ull;
            #pragma unroll
            for (int icp = 0; icp < 8; icp++) {
                u64 fd = pk2(s->p2[(2 * icp) * 49 + pidx],
                             s->p2[(2 * icp + 1) * 49 + pidx]);
                const ulonglong2* wp = (const ulonglong2*)&s->w3p[icp * 32 + half * 2];
                #pragma unroll
                for (int j = 0; j < 8; j++) {
                    ulonglong2 w2 = wp[j * 2];
                    fma2(acc[2*j],   w2.x, fd);
                    fma2(acc[2*j+1], w2.y, fd);
                }
            }
            #pragma unroll
            for (int jp = 0; jp < 8; jp++)
                s->ftp[(half * 8 + jp) * FTS + pos] =
                    pk2(hsum2(acc[2*jp])   + s->b3[half * 16 + 2*jp],
                        hsum2(acc[2*jp+1]) + s->b3[half * 16 + 2*jp + 1]);
        } else {
            #pragma unroll
            for (int jp = 0; jp < 8; jp++)
                s->ftp[(half * 8 + jp) * FTS + pos] =
                    valid_cell ? pk2(s->b3[half * 16 + 2*jp], s->b3[half * 16 + 2*jp + 1])
                               : 0ull;
        }
    }
    __syncthreads();

    // depth-loop roles
    // conf: warp = (row-pair pr, col-half hh); lane = (oct, yp, cp)
    const int pr   = wid >> 1, hh = wid & 1;
    const int octc = lane >> 2;
    const int yp   = (lane >> 1) & 1;
    const int cpi  = lane & 1;
    const int cpos0 = (2 * pr + yp) * 10 + 4 * hh + 2 * cpi;   // conv pos of col pair
    const int ppos  = pr * 4 + 2 * hh + cpi;                   // pooled feature pos
    // a-conv: warps 0-5; lane = (o4 = 8-oc group, pos-pair)
    const int o4 = lane >> 3;
    const int pairk = wid * 8 + (lane & 7);                    // 0..47 for warps 0-5
    const bool aact = wid < 6;

    // ---- Phase 5: adaptive depth loop (2 barriers per depth) ----
    for (int depth = 0; depth < 8; depth++) {
        // --- conf head: GEMM + in-warp 2x2 pool + pooled-dot -> red[wid] ---
        {
            u64 cacc[8][2];
            #pragma unroll
            for (int j = 0; j < 8; j++) { cacc[j][0] = 0ull; cacc[j][1] = 0ull; }
            #pragma unroll 4
            for (int icp = 0; icp < 16; icp++) {
                ulonglong2 fv = *(const ulonglong2*)&s->ftp[icp * FTS + cpos0];
                const ulonglong2* wp = (const ulonglong2*)&s->A.wcfp[icp * 64 + octc * 2];
                #pragma unroll
                for (int j = 0; j < 4; j++) {
                    ulonglong2 w2 = wp[j * 8];          // chunk j: 8 oct groups contiguous
                    fma2(cacc[2*j  ][0], w2.x, fv.x); fma2(cacc[2*j  ][1], w2.x, fv.y);
                    fma2(cacc[2*j+1][0], w2.y, fv.x); fma2(cacc[2*j+1][1], w2.y, fv.y);
                }
            }
            float4 wv0 = *(const float4*)&s->wcfcT[ppos * 68 + octc * 8];
            float4 wv1 = *(const float4*)&s->wcfcT[ppos * 68 + octc * 8 + 4];
            float4 bc0 = *(const float4*)&s->bcf[octc * 8];
            float4 bc1 = *(const float4*)&s->bcf[octc * 8 + 4];
            const float wvv[8] = {wv0.x, wv0.y, wv0.z, wv0.w, wv1.x, wv1.y, wv1.z, wv1.w};
            const float bcv[8] = {bc0.x, bc0.y, bc0.z, bc0.w, bc1.x, bc1.y, bc1.z, bc1.w};
            float partial = 0.f;
            #pragma unroll
            for (int j = 0; j < 8; j++) {
                float m = fmaxf(hsum2(cacc[j][0]), hsum2(cacc[j][1])) + bcv[j];
                m = fmaxf(m, __shfl_xor_sync(0xffffffffu, m, 2));   // row-pair max
                m = fmaxf(m, 0.f);                                  // relu
                partial += m * wvv[j];
            }
            if (yp) partial = 0.f;          // avoid double count across row-parity
            #pragma unroll
            for (int o = 16; o > 0; o >>= 1)
                partial += __shfl_down_sync(0xffffffffu, partial, o);
            if (lane == 0) s->red[wid] = partial;
        }

        // --- a-conv accumulate (warps 0-5), no barrier needed after conf ---
        const int pos0 = 2 * pairk;
        u64 acc[8][2];
        #pragma unroll
        for (int j = 0; j < 8; j++) { acc[j][0] = 0ull; acc[j][1] = 0ull; }
        if (aact) {
            #pragma unroll 4
            for (int icp = 0; icp < 16; icp++) {
                ulonglong2 fv = *(const ulonglong2*)&s->ftp[icp * FTS + pos0];
                const ulonglong2* wp = (const ulonglong2*)&s->B.L.weffp[icp * 32 + o4 * 2];
                ulonglong2 wA = wp[0], wB = wp[4];      // chunks j=0,1
                fma2(acc[0][0], wA.x, fv.x); fma2(acc[0][1], wA.x, fv.y);
                fma2(acc[1][0], wA.y, fv.x); fma2(acc[1][1], wA.y, fv.y);
                fma2(acc[2][0], wB.x, fv.x); fma2(acc[2][1], wB.x, fv.y);
                fma2(acc[3][0], wB.y, fv.x); fma2(acc[3][1], wB.y, fv.y);
                wA = wp[8]; wB = wp[12];                // chunks j=2,3
                fma2(acc[4][0], wA.x, fv.x); fma2(acc[4][1], wA.x, fv.y);
                fma2(acc[5][0], wA.y, fv.x); fma2(acc[5][1], wA.y, fv.y);
                fma2(acc[6][0], wB.x, fv.x); fma2(acc[6][1], wB.x, fv.y);
                fma2(acc[7][0], wB.y, fv.x); fma2(acc[7][1], wB.y, fv.y);
            }
        }
        __syncthreads();   // red visible + all ftp reads complete

        // --- decision: every thread computes the logit (uniform) ---
        {
            float4 r0 = *(const float4*)&s->red[0];
            float4 r1 = *(const float4*)&s->red[4];
            float logit = s->bcfc + r0.x + r0.y + r0.z + r0.w
                                  + r1.x + r1.y + r1.z + r1.w;
            if (logit >= 2.1972245773362196f) break;   // conf >= 0.9 -> frozen
        }

        // --- apply residual: ftp += tanh(acc + beff) ---
        if (aact) {
            #pragma unroll
            for (int m = 0; m < 4; m++) {
                const int row = o4 * 4 + m;                 // icp row = oc pair
                ulonglong2* fp = (ulonglong2*)&s->ftp[row * FTS + pos0];
                ulonglong2 oldv = *fp;
                float e0, e1, f0, f1;
                upk2(oldv.x, e0, e1); upk2(oldv.y, f0, f1);
                float b0 = s->B.L.beff[o4 * 8 + 2*m];
                float b1 = s->B.L.beff[o4 * 8 + 2*m + 1];
                oldv.x = pk2(e0 + fast_tanh(hsum2(acc[2*m][0])   + b0),
                             e1 + fast_tanh(hsum2(acc[2*m+1][0]) + b1));
                oldv.y = pk2(f0 + fast_tanh(hsum2(acc[2*m][1])   + b0),
                             f1 + fast_tanh(hsum2(acc[2*m+1][1]) + b1));
                *fp = oldv;
            }
        }
        __syncthreads();   // writes visible before next depth's reads
    }

    // ---- Phase 6: classifier (float4 LDG over w_cls) ----
    {
        const float* ftf = (const float*)s->ftp;
        float ac[10];
        #pragma unroll
        for (int o = 0; o < 10; o++) ac[o] = 0.f;
        #pragma unroll
        for (int k = 0; k < 3; k++) {
            int i4 = tid + k * NT;
            if (i4 < 648) {
                int i = i4 * 4;
                float fv[4];
                #pragma unroll
                for (int t = 0; t < 4; t++) {
                    int ii = i + t;
                    int ch = ii / 81;
                    int r  = ii - ch * 81;
                    int y  = r / 9, x = r - 9 * y;
                    fv[t] = ftf[(ch >> 1) * (2 * FTS) + (y * 10 + x) * 2 + (ch & 1)];
                }
                #pragma unroll
                for (int o = 0; o < 10; o++) {
                    float4 w4 = *(const float4*)&gwcls[o * 2592 + i];
                    ac[o] += w4.x * fv[0] + w4.y * fv[1] + w4.z * fv[2] + w4.w * fv[3];
                }
            }
        }
        #pragma unroll
        for (int o = 0; o < 10; o++) {
            float v = ac[o];
            #pragma unroll
            for (int sh = 16; sh > 0; sh >>= 1)
                v += __shfl_down_sync(0xffffffffu, v, sh);
            if (lane == 0) s->clsred[wid * 10 + o] = v;
        }
        __syncthreads();
        if (tid < 10) {
            float v = gbcls[tid];
            #pragma unroll
            for (int w = 0; w < 8; w++) v += s->clsred[w * 10 + tid];
            gout[(size_t)b * 10 + tid] = v;
        }
    }
}

extern "C" void kernel_launch(void* const* d_in, const int* in_sizes, int n_in,
                              void* d_out, int out_size) {
    const float* x     = (const float*)d_in[0];
    const float* w_b1  = (const float*)d_in[1];
    const float* b_b1  = (const float*)d_in[2];
    const float* w_b2  = (const float*)d_in[3];
    const float* b_b2  = (const float*)d_in[4];
    const float* w_b3  = (const float*)d_in[5];
    const float* b_b3  = (const float*)d_in[6];
    const float* w_cf  = (const float*)d_in[7];
    const float* b_cf  = (const float*)d_in[8];
    const float* w_cfc = (const float*)d_in[9];
    const float* b_cfc = (const float*)d_in[10];
    const float* w_q   = (const float*)d_in[11];
    const float* b_q   = (const float*)d_in[12];
    const float* w_a   = (const float*)d_in[13];
    const float* b_a   = (const float*)d_in[14];
    const float* w_cls = (const float*)d_in[15];
    const float* b_cls = (const float*)d_in[16];
    float* out = (float*)d_out;

    int B = in_sizes[0] / (3 * 32 * 32);
    size_t smem = sizeof(Smem);
    cudaFuncSetAttribute(TM_20005957665089_kernel,
                         cudaFuncAttributeMaxDynamicSharedMemorySize, (int)smem);
    TM_20005957665089_kernel<<<B, NT, smem>>>(
        x, w_b1, b_b1, w_b2, b_b2, w_b3, b_b3,
        w_cf, b_cf, w_cfc, b_cfc, w_q, b_q, w_a, b_a,
        w_cls, b_cls, out);
}

// round 10
// speedup vs baseline: 1.1574x; 1.0873x over previous
#include <cuda_runtime.h>
#include <math.h>

#define NT 256
#define FTS 98    // ftp row stride in u64 (784B, bank drift 4 -> 2-way max on RMW)
typedef unsigned long long u64;

__device__ __forceinline__ u64 pk2(float lo, float hi) {
    u64 r; asm("mov.b64 %0,{%1,%2};" : "=l"(r) : "f"(lo), "f"(hi)); return r;
}
__device__ __forceinline__ void upk2(u64 v, float& lo, float& hi) {
    asm("mov.b64 {%0,%1},%2;" : "=f"(lo), "=f"(hi) : "l"(v));
}
__device__ __forceinline__ void fma2(u64& d, u64 a, u64 b) {
    asm("fma.rn.f32x2 %0,%1,%2,%0;" : "+l"(d) : "l"(a), "l"(b));
}
__device__ __forceinline__ float hsum2(u64 v) {
    float lo, hi; upk2(v, lo, hi); return lo + hi;
}
__device__ __forceinline__ float fast_tanh(float x) {
    float t, r;
    asm("ex2.approx.f32 %0, %1;" : "=f"(t) : "f"(x * 2.885390082f));
    asm("rcp.approx.f32 %0, %1;" : "=f"(r) : "f"(t + 1.0f));
    return 1.0f - 2.0f * r;
}

struct __align__(16) Smem {
    union {
        float xs[3 * 34 * 34];       // phases 1-2 (13872B)
        u64   wcfp[16 * 64];         // depth loop: [icp][j][o8grp] interleaved (8192B)
    } A;
    union {
        float p1p[8 * 17 * 17];      // phases 2-3 (9248B)
        struct { u64 weffp[16 * 32]; float beff[32]; } L;  // depth loop (4224B)
    } B;
    union {
        float p2[16 * 49];           // phases 3-4 (3136B)
        struct { float red[8]; float clsred[80]; } R;      // depth loop + classifier
    } C;
    u64    ftp[16 * FTS];            // feature map [icp][pos], pos = y*10+x (12544B)
    float2 w1d[600];                 // conv1 [tap][oc8] dup pairs (4800B)
    float  w2f[72 * 16];             // conv2 [tap][oc] plain floats (4608B)
    u64    w3p[8 * 32];              // conv3 [icp][j][half] interleaved (2048B)
    float  wcfcT[16 * 64];           // conf fc weights transposed [pooledpos][oc] (4096B)
    float  bcf[64];
    float  b1[8], b2[16], b3[32];
    float  bcfc;
};

__global__ __launch_bounds__(NT, 4)
void TM_20005957665089_kernel(
    const float* __restrict__ gx,
    const float* __restrict__ gw1,  const float* __restrict__ gb1,
    const float* __restrict__ gw2,  const float* __restrict__ gb2,
    const float* __restrict__ gw3,  const float* __restrict__ gb3,
    const float* __restrict__ gwcf, const float* __restrict__ gbcf,
    const float* __restrict__ gwcfc,const float* __restrict__ gbcfc,
    const float* __restrict__ gwq,  const float* __restrict__ gbq,
    const float* __restrict__ gwa,  const float* __restrict__ gba,
    const float* __restrict__ gwcls,const float* __restrict__ gbcls,
    float* __restrict__ gout)
{
    extern __shared__ float smem_raw[];
    Smem* s = reinterpret_cast<Smem*>(smem_raw);
    const int tid  = threadIdx.x;
    const int lane = tid & 31;
    const int wid  = tid >> 5;
    const int b    = blockIdx.x;

    // ---- Phase 0 ----
    for (int i = tid; i < 3468; i += NT) s->A.xs[i]  = 0.f;
    for (int i = tid; i < 2312; i += NT) s->B.p1p[i] = 0.f;
    for (int i = tid; i < 600; i += NT) {
        int oc = i / 75, r = i % 75;
        float v = gw1[i];
        s->w1d[r * 8 + oc] = make_float2(v, v);
    }
    for (int i = tid; i < 1152; i += NT) {
        int oc = i / 72, r = i % 72;
        s->w2f[r * 16 + oc] = gw2[i];
    }
    // w3p interleaved: entry (icp, oc) at u64 idx icp*32 + j*4 + half*2 + (oc&1)
    for (int i = tid; i < 512; i += NT) {
        int oc = i >> 4, ic = i & 15;
        int u = (ic >> 1) * 32 + ((oc & 15) >> 1) * 4 + (oc >> 4) * 2 + (oc & 1);
        ((float*)s->w3p)[u * 2 + (ic & 1)] = gw3[i];
    }
    // wcfcT[p][oc] = w_cfc[oc*16 + p]
    for (int i = tid; i < 1024; i += NT) {
        int p = i >> 6, c = i & 63;
        s->wcfcT[p * 64 + c] = gwcfc[c * 16 + p];
    }
    for (int i = tid; i < 64; i += NT) s->bcf[i] = gbcf[i];
    if (tid < 8)  s->b1[tid] = gb1[tid];
    if (tid < 16) s->b2[tid] = gb2[tid];
    if (tid < 32) s->b3[tid] = gb3[tid];
    if (tid == 0) s->bcfc = gbcfc[0];
    __syncthreads();

    // ---- Phase 1: x -> padded smem ----
    const float* xin = gx + (size_t)b * 3072;
    for (int i = tid; i < 3072; i += NT) {
        int c = i >> 10, r = (i >> 5) & 31, cc = i & 31;
        s->A.xs[c * 1156 + (r + 1) * 34 + (cc + 1)] = xin[i];
    }
    __syncthreads();

    // ---- Phase 2: conv1 (3->8, 5x5) + relu + maxpool2, 2 oc-passes (reg cap) ----
    if (tid < 225) {
        const int py = tid / 15, px = tid % 15;
        const int x0 = 2 * px, y0 = 2 * py;
        #pragma unroll
        for (int h = 0; h < 2; h++) {          // oc half: oc = h*4 + k
            u64 acc[4][2];
            #pragma unroll
            for (int k = 0; k < 4; k++) { acc[k][0] = 0ull; acc[k][1] = 0ull; }
            #pragma unroll
            for (int ic = 0; ic < 3; ic++) {
                const float* xb = &s->A.xs[ic * 1156 + y0 * 34 + x0];   // 8B-aligned
                #pragma unroll
                for (int ky = 0; ky < 5; ky++) {
                    const u64* pa64 = (const u64*)(xb + ky * 34);
                    const u64* pb64 = (const u64*)(xb + ky * 34 + 34);
                    u64 A0 = pa64[0], A1 = pa64[1], A2 = pa64[2];
                    u64 B0 = pb64[0], B1 = pb64[1], B2 = pb64[2];
                    float al0,ah0,al1,ah1,al2,ah2, bl0,bh0,bl1,bh1,bl2,bh2;
                    upk2(A0,al0,ah0); upk2(A1,al1,ah1); upk2(A2,al2,ah2);
                    upk2(B0,bl0,bh0); upk2(B1,bl1,bh1); upk2(B2,bl2,bh2);
                    u64 pa2[5] = { A0, pk2(ah0, al1), A1, pk2(ah1, al2), A2 };
                    u64 pb2[5] = { B0, pk2(bh0, bl1), B1, pk2(bh1, bl2), B2 };
                    const ulonglong2* wp =
                        (const ulonglong2*)&s->w1d[(ic * 25 + ky * 5) * 8 + h * 4];
                    #pragma unroll
                    for (int kx = 0; kx < 5; kx++) {
                        #pragma unroll
                        for (int j = 0; j < 2; j++) {
                            ulonglong2 w2 = wp[kx * 4 + j];
                            fma2(acc[2*j  ][0], w2.x, pa2[kx]);
                            fma2(acc[2*j  ][1], w2.x, pb2[kx]);
                            fma2(acc[2*j+1][0], w2.y, pa2[kx]);
                            fma2(acc[2*j+1][1], w2.y, pb2[kx]);
                        }
                    }
                }
            }
            #pragma unroll
            for (int k = 0; k < 4; k++) {
                float a0, a1, c0, c1;
                upk2(acc[k][0], a0, a1); upk2(acc[k][1], c0, c1);
                float m = fmaxf(fmaxf(a0, a1), fmaxf(c0, c1)) + s->b1[h * 4 + k];
                s->B.p1p[(h * 4 + k) * 289 + (py + 1) * 17 + (px + 1)] = fmaxf(m, 0.f);
            }
        }
    }
    __syncthreads();

    // ---- Phase 2.5 (xs dead): wcfp interleaved fill + conv2 ----
    // entry (icp, oc) at u64 idx icp*64 + j*16 + g*2 + (oc&1), j=(oc&7)>>1, g=oc>>3
    for (int i = tid; i < 1024; i += NT) {
        int icp = i >> 6, oc = i & 63;
        int u = icp * 64 + ((oc & 7) >> 1) * 16 + (oc >> 3) * 2 + (oc & 1);
        s->A.wcfp[u] = pk2(gwcf[oc * 32 + 2 * icp], gwcf[oc * 32 + 2 * icp + 1]);
    }
    if (tid < 196) {
        const int ocg = tid / 49;
        const int pos = tid % 49;
        const int py = pos / 7, px = pos % 7;
        u64 acc[4][2];
        #pragma unroll
        for (int k = 0; k < 4; k++) { acc[k][0] = 0ull; acc[k][1] = 0ull; }
        #pragma unroll
        for (int ic = 0; ic < 8; ic++) {
            const float* pbase = &s->B.p1p[ic * 289 + 2 * py * 17 + 2 * px];
            #pragma unroll
            for (int ky = 0; ky < 3; ky++) {
                const float* pa = pbase + ky * 17;
                const float* pb = pa + 17;
                u64 pa2[3], pb2[3];
                #pragma unroll
                for (int kx = 0; kx < 3; kx++) {
                    pa2[kx] = pk2(pa[kx], pa[kx + 1]);
                    pb2[kx] = pk2(pb[kx], pb[kx + 1]);
                }
                #pragma unroll
                for (int kx = 0; kx < 3; kx++) {
                    float4 wv = *(const float4*)
                        &s->w2f[(ic * 9 + ky * 3 + kx) * 16 + ocg * 4];
                    u64 d0 = pk2(wv.x, wv.x), d1 = pk2(wv.y, wv.y);
                    u64 d2 = pk2(wv.z, wv.z), d3 = pk2(wv.w, wv.w);
                    fma2(acc[0][0], d0, pa2[kx]); fma2(acc[0][1], d0, pb2[kx]);
                    fma2(acc[1][0], d1, pa2[kx]); fma2(acc[1][1], d1, pb2[kx]);
                    fma2(acc[2][0], d2, pa2[kx]); fma2(acc[2][1], d2, pb2[kx]);
                    fma2(acc[3][0], d3, pa2[kx]); fma2(acc[3][1], d3, pb2[kx]);
                }
            }
        }
        #pragma unroll
        for (int k = 0; k < 4; k++) {
            float a0, a1, c0, c1;
            upk2(acc[k][0], a0, a1); upk2(acc[k][1], c0, c1);
            float m = fmaxf(fmaxf(a0, a1), fmaxf(c0, c1)) + s->b2[ocg * 4 + k];
            s->C.p2[(ocg * 4 + k) * 49 + pos] = fmaxf(m, 0.f);
        }
    }
    __syncthreads();

    // ---- Phase 3.5 (p1p dead): weffp interleaved fill + conv3 -> ftp ----
    for (int o = tid; o < 1024; o += NT) {
        int oc = o >> 5, ic = o & 31;
        float v = __ldg(&gwa[oc * 48 + 16 + ic]);
        #pragma unroll
        for (int j = 0; j < 16; j++)
            v += __ldg(&gwa[oc * 48 + j]) * __ldg(&gwq[j * 32 + ic]);
        int u = (ic >> 1) * 32 + ((oc & 7) >> 1) * 8 + (oc >> 3) * 2 + (oc & 1);
        ((float*)s->B.L.weffp)[u * 2 + (ic & 1)] = v;
    }
    if (tid < 32) {
        float v = __ldg(&gba[tid]);
        #pragma unroll
        for (int j = 0; j < 16; j++)
            v += __ldg(&gwa[tid * 48 + j]) * __ldg(&gbq[j]);
        s->B.L.beff[tid] = v;
    }
    // conv3: thread = (pos 0..95, half of 16 oc), 2 passes of 8 oc (reg cap)
    if (tid < 192) {
        const int pos  = tid >> 1;
        const int half = tid & 1;
        const int y = pos / 10, x = pos % 10;
        const bool valid_cell = (x < 9) && (y < 9);
        const bool interior = ((unsigned)(y - 1) < 7u) && ((unsigned)(x - 1) < 7u);
        if (interior) {
            const int pidx = (y - 1) * 7 + (x - 1);
            #pragma unroll
            for (int hp = 0; hp < 2; hp++) {     // 8 oc per pass
                u64 acc[8];
                #pragma unroll
                for (int k = 0; k < 8; k++) acc[k] = 0ull;
                #pragma unroll
                for (int icp = 0; icp < 8; icp++) {
                    u64 fd = pk2(s->C.p2[(2 * icp) * 49 + pidx],
                                 s->C.p2[(2 * icp + 1) * 49 + pidx]);
                    const ulonglong2* wp =
                        (const ulonglong2*)&s->w3p[icp * 32 + half * 2];
                    #pragma unroll
                    for (int j = 0; j < 4; j++) {
                        ulonglong2 w2 = wp[(hp * 4 + j) * 2];
                        fma2(acc[2*j],   w2.x, fd);
                        fma2(acc[2*j+1], w2.y, fd);
                    }
                }
                #pragma unroll
                for (int jp = 0; jp < 4; jp++)
                    s->ftp[(half * 8 + hp * 4 + jp) * FTS + pos] =
                        pk2(hsum2(acc[2*jp])   + s->b3[half*16 + hp*8 + 2*jp],
                            hsum2(acc[2*jp+1]) + s->b3[half*16 + hp*8 + 2*jp + 1]);
            }
        } else {
            #pragma unroll
            for (int jp = 0; jp < 8; jp++)
                s->ftp[(half * 8 + jp) * FTS + pos] =
                    valid_cell ? pk2(s->b3[half * 16 + 2*jp], s->b3[half * 16 + 2*jp + 1])
                               : 0ull;
        }
    }
    __syncthreads();

    // depth-loop roles
    // conf: warp = (row-pair pr, col-half hh); lane = (oct, yp, cp)
    const int pr   = wid >> 1, hh = wid & 1;
    const int octc = lane >> 2;
    const int yp   = (lane >> 1) & 1;
    const int cpi  = lane & 1;
    const int cpos0 = (2 * pr + yp) * 10 + 4 * hh + 2 * cpi;   // conv pos of col pair
    const int ppos  = pr * 4 + 2 * hh + cpi;                   // pooled feature pos
    // a-conv: warps 0-5; lane = (o4 = 8-oc group, pos-pair)
    const int o4 = lane >> 3;
    const int pairk = wid * 8 + (lane & 7);                    // 0..47 for warps 0-5
    const bool aact = wid < 6;

    // ---- Phase 5: adaptive depth loop (2 barriers per depth) ----
    for (int depth = 0; depth < 8; depth++) {
        // --- conf head: GEMM + in-warp 2x2 pool + pooled-dot -> red[wid] ---
        {
            u64 cacc[8][2];
            #pragma unroll
            for (int j = 0; j < 8; j++) { cacc[j][0] = 0ull; cacc[j][1] = 0ull; }
            #pragma unroll 4
            for (int icp = 0; icp < 16; icp++) {
                ulonglong2 fv = *(const ulonglong2*)&s->ftp[icp * FTS + cpos0];
                const ulonglong2* wp = (const ulonglong2*)&s->A.wcfp[icp * 64 + octc * 2];
                #pragma unroll
                for (int j = 0; j < 4; j++) {
                    ulonglong2 w2 = wp[j * 8];          // chunk j: 8 oct groups contiguous
                    fma2(cacc[2*j  ][0], w2.x, fv.x); fma2(cacc[2*j  ][1], w2.x, fv.y);
                    fma2(cacc[2*j+1][0], w2.y, fv.x); fma2(cacc[2*j+1][1], w2.y, fv.y);
                }
            }
            float4 wv0 = *(const float4*)&s->wcfcT[ppos * 64 + octc * 8];
            float4 wv1 = *(const float4*)&s->wcfcT[ppos * 64 + octc * 8 + 4];
            float4 bc0 = *(const float4*)&s->bcf[octc * 8];
            float4 bc1 = *(const float4*)&s->bcf[octc * 8 + 4];
            const float wvv[8] = {wv0.x, wv0.y, wv0.z, wv0.w, wv1.x, wv1.y, wv1.z, wv1.w};
            const float bcv[8] = {bc0.x, bc0.y, bc0.z, bc0.w, bc1.x, bc1.y, bc1.z, bc1.w};
            float partial = 0.f;
            #pragma unroll
            for (int j = 0; j < 8; j++) {
                float m = fmaxf(hsum2(cacc[j][0]), hsum2(cacc[j][1])) + bcv[j];
                m = fmaxf(m, __shfl_xor_sync(0xffffffffu, m, 2));   // row-pair max
                m = fmaxf(m, 0.f);                                  // relu
                partial += m * wvv[j];
            }
            if (yp) partial = 0.f;          // avoid double count across row-parity
            #pragma unroll
            for (int o = 16; o > 0; o >>= 1)
                partial += __shfl_down_sync(0xffffffffu, partial, o);
            if (lane == 0) s->C.R.red[wid] = partial;
        }

        // --- a-conv accumulate (warps 0-5), no barrier needed after conf ---
        const int pos0 = 2 * pairk;
        u64 acc[8][2];
        #pragma unroll
        for (int j = 0; j < 8; j++) { acc[j][0] = 0ull; acc[j][1] = 0ull; }
        if (aact) {
            #pragma unroll 4
            for (int icp = 0; icp < 16; icp++) {
                ulonglong2 fv = *(const ulonglong2*)&s->ftp[icp * FTS + pos0];
                const ulonglong2* wp = (const ulonglong2*)&s->B.L.weffp[icp * 32 + o4 * 2];
                ulonglong2 wA = wp[0], wB = wp[4];      // chunks j=0,1
                fma2(acc[0][0], wA.x, fv.x); fma2(acc[0][1], wA.x, fv.y);
                fma2(acc[1][0], wA.y, fv.x); fma2(acc[1][1], wA.y, fv.y);
                fma2(acc[2][0], wB.x, fv.x); fma2(acc[2][1], wB.x, fv.y);
                fma2(acc[3][0], wB.y, fv.x); fma2(acc[3][1], wB.y, fv.y);
                wA = wp[8]; wB = wp[12];                // chunks j=2,3
                fma2(acc[4][0], wA.x, fv.x); fma2(acc[4][1], wA.x, fv.y);
                fma2(acc[5][0], wA.y, fv.x); fma2(acc[5][1], wA.y, fv.y);
                fma2(acc[6][0], wB.x, fv.x); fma2(acc[6][1], wB.x, fv.y);
                fma2(acc[7][0], wB.y, fv.x); fma2(acc[7][1], wB.y, fv.y);
            }
        }
        __syncthreads();   // red visible + all ftp reads complete

        // --- decision: every thread computes the logit (uniform) ---
        {
            float4 r0 = *(const float4*)&s->C.R.red[0];
            float4 r1 = *(const float4*)&s->C.R.red[4];
            float logit = s->bcfc + r0.x + r0.y + r0.z + r0.w
                                  + r1.x + r1.y + r1.z + r1.w;
            if (logit >= 2.1972245773362196f) break;   // conf >= 0.9 -> frozen
        }

        // --- apply residual: ftp += tanh(acc + beff) ---
        if (aact) {
            #pragma unroll
            for (int m = 0; m < 4; m++) {
                const int row = o4 * 4 + m;                 // icp row = oc pair
                ulonglong2* fp = (ulonglong2*)&s->ftp[row * FTS + pos0];
                ulonglong2 oldv = *fp;
                float e0, e1, f0, f1;
                upk2(oldv.x, e0, e1); upk2(oldv.y, f0, f1);
                float b0 = s->B.L.beff[o4 * 8 + 2*m];
                float b1 = s->B.L.beff[o4 * 8 + 2*m + 1];
                oldv.x = pk2(e0 + fast_tanh(hsum2(acc[2*m][0])   + b0),
                             e1 + fast_tanh(hsum2(acc[2*m+1][0]) + b1));
                oldv.y = pk2(f0 + fast_tanh(hsum2(acc[2*m][1])   + b0),
                             f1 + fast_tanh(hsum2(acc[2*m+1][1]) + b1));
                *fp = oldv;
            }
        }
        __syncthreads();   // writes visible before next depth's reads
    }

    // ---- Phase 6: classifier (float4 LDG over w_cls) ----
    {
        const float* ftf = (const float*)s->ftp;
        float ac[10];
        #pragma unroll
        for (int o = 0; o < 10; o++) ac[o] = 0.f;
        #pragma unroll
        for (int k = 0; k < 3; k++) {
            int i4 = tid + k * NT;
            if (i4 < 648) {
                int i = i4 * 4;
                float fv[4];
                #pragma unroll
                for (int t = 0; t < 4; t++) {
                    int ii = i + t;
                    int ch = ii / 81;
                    int r  = ii - ch * 81;
                    int y  = r / 9, x = r - 9 * y;
                    fv[t] = ftf[(ch >> 1) * (2 * FTS) + (y * 10 + x) * 2 + (ch & 1)];
                }
                #pragma unroll
                for (int o = 0; o < 10; o++) {
                    float4 w4 = *(const float4*)&gwcls[o * 2592 + i];
                    ac[o] += w4.x * fv[0] + w4.y * fv[1] + w4.z * fv[2] + w4.w * fv[3];
                }
            }
        }
        #pragma unroll
        for (int o = 0; o < 10; o++) {
            float v = ac[o];
            #pragma unroll
            for (int sh = 16; sh > 0; sh >>= 1)
                v += __shfl_down_sync(0xffffffffu, v, sh);
            if (lane == 0) s->C.R.clsred[wid * 10 + o] = v;
        }
        __syncthreads();
        if (tid < 10) {
            float v = gbcls[tid];
            #pragma unroll
            for (int w = 0; w < 8; w++) v += s->C.R.clsred[w * 10 + tid];
            gout[(size_t)b * 10 + tid] = v;
        }
    }
}

extern "C" void kernel_launch(void* const* d_in, const int* in_sizes, int n_in,
                              void* d_out, int out_size) {
    const float* x     = (const float*)d_in[0];
    const float* w_b1  = (const float*)d_in[1];
    const float* b_b1  = (const float*)d_in[2];
    const float* w_b2  = (const float*)d_in[3];
    const float* b_b2  = (const float*)d_in[4];
    const float* w_b3  = (const float*)d_in[5];
    const float* b_b3  = (const float*)d_in[6];
    const float* w_cf  = (const float*)d_in[7];
    const float* b_cf  = (const float*)d_in[8];
    const float* w_cfc = (const float*)d_in[9];
    const float* b_cfc = (const float*)d_in[10];
    const float* w_q   = (const float*)d_in[11];
    const float* b_q   = (const float*)d_in[12];
    const float* w_a   = (const float*)d_in[13];
    const float* b_a   = (const float*)d_in[14];
    const float* w_cls = (const float*)d_in[15];
    const float* b_cls = (const float*)d_in[16];
    float* out = (float*)d_out;

    int B = in_sizes[0] / (3 * 32 * 32);
    size_t smem = sizeof(Smem);
    cudaFuncSetAttribute(TM_20005957665089_kernel,
                         cudaFuncAttributeMaxDynamicSharedMemorySize, (int)smem);
    TM_20005957665089_kernel<<<B, NT, smem>>>(
        x, w_b1, b_b1, w_b2, b_b2, w_b3, b_b3,
        w_cf, b_cf, w_cfc, b_cfc, w_q, b_q, w_a, b_a,
        w_cls, b_cls, out);
}